// round 2
// baseline (speedup 1.0000x reference)
#include <cuda_runtime.h>

#define NN 50000
#define NE 800000
#define NG 128
#define DIN 96

// Scratch (allocation-free rule: __device__ globals)
__device__ float g_agg[NN * DIN];
__device__ float g_ha[NN * DIN];
__device__ float g_hb[NN * DIN];
__device__ float g_inv_deg[NN];
__device__ float g_inv_cnt[NG];

static inline int cdiv(int a, int b) { return (a + b - 1) / b; }

__global__ void zero_kernel(float* __restrict__ p, int n) {
    int i = blockIdx.x * blockDim.x + threadIdx.x;
    if (i < n) p[i] = 0.0f;
}

__global__ void deg_kernel(const int* __restrict__ dst) {
    int i = blockIdx.x * blockDim.x + threadIdx.x;
    if (i < NE) atomicAdd(&g_inv_deg[dst[i]], 1.0f);
}

__global__ void cnt_kernel(const int* __restrict__ batch) {
    int i = blockIdx.x * blockDim.x + threadIdx.x;
    if (i < NN) atomicAdd(&g_inv_cnt[batch[i]], 1.0f);
}

__global__ void invert_kernel(float* __restrict__ p, int n) {
    int i = blockIdx.x * blockDim.x + threadIdx.x;
    if (i < n) p[i] = 1.0f / fmaxf(p[i], 1.0f);
}

// One warp per edge: lane covers cols {lane, lane+32, lane+64} (coalesced 128B)
__global__ void scatter_kernel(const float* __restrict__ x,
                               const int* __restrict__ src,
                               const int* __restrict__ dst) {
    int gw = (blockIdx.x * blockDim.x + threadIdx.x) >> 5;
    int lane = threadIdx.x & 31;
    if (gw >= NE) return;
    int s = __ldg(&src[gw]);
    int t = __ldg(&dst[gw]);
    const float* xr = x + (size_t)s * DIN;
    float* ar = g_agg + (size_t)t * DIN;
    float v0 = __ldg(xr + lane);
    float v1 = __ldg(xr + lane + 32);
    float v2 = __ldg(xr + lane + 64);
    atomicAdd(ar + lane,      v0);
    atomicAdd(ar + lane + 32, v1);
    atomicAdd(ar + lane + 64, v2);
}

// Fused SAGE layer: out[n][j] = relu?( b[j] + sum_k mean[n][k]*Wl[j][k] + x[n][k]*Wr[j][k] )
// Block: 64 nodes x DOUT outs; 256 threads as 16x16; thread: 4 nodes x (DOUT/16) outs.
template<int DOUT, bool RELU>
__global__ void __launch_bounds__(256)
sage_gemm(const float* __restrict__ xin,
          const float* __restrict__ agg,
          const float* __restrict__ inv_deg,
          const float* __restrict__ Wl,
          const float* __restrict__ bias,
          const float* __restrict__ Wr,
          float* __restrict__ out) {
    constexpr int WP = DOUT + 1;   // padded pitch: conflict-free transposed W
    constexpr int NJ = DOUT / 16;  // 6 (d=96) or 4 (d=64)
    extern __shared__ float sm[];
    float* Wlt = sm;                   // [96][WP]  (k-major, transposed)
    float* Wrt = Wlt + DIN * WP;       // [96][WP]
    float* bs  = Wrt + DIN * WP;       // [DOUT]
    float* Am  = bs + DOUT;            // [64][97]  mean tile
    float* Ax  = Am + 64 * 97;         // [64][97]  x tile

    int tid = threadIdx.x;

    // Coalesced gmem read of W (row-major [DOUT][96]), transposed smem write
    // (write stride WP=DOUT+1 -> bank-conflict-free)
    for (int idx = tid; idx < DOUT * DIN; idx += 256) {
        int j = idx / DIN, k = idx - j * DIN;
        Wlt[k * WP + j] = Wl[idx];
        Wrt[k * WP + j] = Wr[idx];
    }
    if (tid < DOUT) bs[tid] = bias[tid];

    int node0 = blockIdx.x * 64;
    for (int idx = tid; idx < 64 * DIN; idx += 256) {
        int n = idx / DIN, k = idx - n * DIN;
        int node = node0 + n;
        float a = 0.0f, xv = 0.0f;
        if (node < NN) {
            a  = agg[(size_t)node * DIN + k] * __ldg(&inv_deg[node]);
            xv = xin[(size_t)node * DIN + k];
        }
        Am[n * 97 + k] = a;
        Ax[n * 97 + k] = xv;
    }
    __syncthreads();

    int tx = tid & 15, ty = tid >> 4;
    float acc[4][NJ];
#pragma unroll
    for (int nn = 0; nn < 4; nn++)
#pragma unroll
        for (int jj = 0; jj < NJ; jj++)
            acc[nn][jj] = bs[jj * 16 + tx];

#pragma unroll 4
    for (int k = 0; k < DIN; k++) {
        float am[4], ax[4];
#pragma unroll
        for (int nn = 0; nn < 4; nn++) {
            int n = nn * 16 + ty;
            am[nn] = Am[n * 97 + k];
            ax[nn] = Ax[n * 97 + k];
        }
#pragma unroll
        for (int jj = 0; jj < NJ; jj++) {
            float wl = Wlt[k * WP + jj * 16 + tx];
            float wr = Wrt[k * WP + jj * 16 + tx];
#pragma unroll
            for (int nn = 0; nn < 4; nn++)
                acc[nn][jj] += am[nn] * wl;
#pragma unroll
            for (int nn = 0; nn < 4; nn++)
                acc[nn][jj] += ax[nn] * wr;
        }
    }

#pragma unroll
    for (int nn = 0; nn < 4; nn++) {
        int node = node0 + nn * 16 + ty;
        if (node < NN) {
#pragma unroll
            for (int jj = 0; jj < NJ; jj++) {
                float v = acc[nn][jj];
                if (RELU) v = fmaxf(v, 0.0f);
                out[(size_t)node * DOUT + jj * 16 + tx] = v;
            }
        }
    }
}

// global mean pool: out[g][j] += h[n][j] * inv_cnt[g]
__global__ void pool_kernel(const float* __restrict__ h,
                            const int* __restrict__ batch,
                            float* __restrict__ out) {
    int i = blockIdx.x * blockDim.x + threadIdx.x;
    if (i >= NN * 64) return;
    int node = i >> 6, j = i & 63;
    int g = __ldg(&batch[node]);
    atomicAdd(&out[g * 64 + j], h[i] * g_inv_cnt[g]);
}

extern "C" void kernel_launch(void* const* d_in, const int* in_sizes, int n_in,
                              void* d_out, int out_size) {
    const float* x     = (const float*)d_in[0];
    const int*   ei    = (const int*)d_in[1];
    const int*   batch = (const int*)d_in[2];
    const float* Wl0 = (const float*)d_in[3];
    const float* b0  = (const float*)d_in[4];
    const float* Wr0 = (const float*)d_in[5];
    const float* Wl1 = (const float*)d_in[6];
    const float* b1  = (const float*)d_in[7];
    const float* Wr1 = (const float*)d_in[8];
    const float* Wl2 = (const float*)d_in[9];
    const float* b2  = (const float*)d_in[10];
    const float* Wr2 = (const float*)d_in[11];
    float* out = (float*)d_out;

    const int* srcp = ei;
    const int* dstp = ei + NE;

    float *agg, *ha, *hb, *invdeg, *invcnt;
    cudaGetSymbolAddress((void**)&agg,    g_agg);
    cudaGetSymbolAddress((void**)&ha,     g_ha);
    cudaGetSymbolAddress((void**)&hb,     g_hb);
    cudaGetSymbolAddress((void**)&invdeg, g_inv_deg);
    cudaGetSymbolAddress((void**)&invcnt, g_inv_cnt);

    const int SMEM96 = (2 * DIN * 97 + 96 + 2 * 64 * 97) * (int)sizeof(float);
    const int SMEM64 = (2 * DIN * 65 + 64 + 2 * 64 * 97) * (int)sizeof(float);
    cudaFuncSetAttribute(sage_gemm<96, true>,
                         cudaFuncAttributeMaxDynamicSharedMemorySize, SMEM96);
    cudaFuncSetAttribute(sage_gemm<64, false>,
                         cudaFuncAttributeMaxDynamicSharedMemorySize, SMEM64);

    const int T = 256;
    int gemm_grid = cdiv(NN, 64);

    // degrees + graph counts
    zero_kernel<<<cdiv(NN, T), T>>>(invdeg, NN);
    zero_kernel<<<cdiv(NG, T), T>>>(invcnt, NG);
    deg_kernel<<<cdiv(NE, T), T>>>(dstp);
    cnt_kernel<<<cdiv(NN, T), T>>>(batch);
    invert_kernel<<<cdiv(NN, T), T>>>(invdeg, NN);
    invert_kernel<<<cdiv(NG, T), T>>>(invcnt, NG);

    // layer 0: x -> ha
    zero_kernel<<<cdiv(NN * DIN, T), T>>>(agg, NN * DIN);
    scatter_kernel<<<cdiv(NE * 32, T), T>>>(x, srcp, dstp);
    sage_gemm<96, true><<<gemm_grid, T, SMEM96>>>(x, agg, invdeg, Wl0, b0, Wr0, ha);

    // layer 1: ha -> hb
    zero_kernel<<<cdiv(NN * DIN, T), T>>>(agg, NN * DIN);
    scatter_kernel<<<cdiv(NE * 32, T), T>>>(ha, srcp, dstp);
    sage_gemm<96, true><<<gemm_grid, T, SMEM96>>>(ha, agg, invdeg, Wl1, b1, Wr1, hb);

    // layer 2: hb -> ha (reused, [NN,64])
    zero_kernel<<<cdiv(NN * DIN, T), T>>>(agg, NN * DIN);
    scatter_kernel<<<cdiv(NE * 32, T), T>>>(hb, srcp, dstp);
    sage_gemm<64, false><<<gemm_grid, T, SMEM64>>>(hb, agg, invdeg, Wl2, b2, Wr2, ha);

    // global mean pool
    zero_kernel<<<cdiv(NG * 64, T), T>>>(out, NG * 64);
    pool_kernel<<<cdiv(NN * 64, T), T>>>(ha, batch, out);
}

// round 3
// speedup vs baseline: 1.4079x; 1.4079x over previous
#include <cuda_runtime.h>

#define NN 50000
#define NE 800000
#define NG 128
#define DIN 96
#define SCAN_B 1024
#define NBLK ((NN + SCAN_B - 1) / SCAN_B)   // 49

// ---- scratch (__device__ globals; no allocs allowed) ----
__device__ float g_agg[NN * DIN];     // mean-aggregated features
__device__ float g_ha[NN * DIN];
__device__ float g_hb[NN * DIN];
__device__ int   g_cnt[NN];           // per-node in-degree (histogram)
__device__ int   g_excl[NBLK * SCAN_B];
__device__ int   g_bsum[64];
__device__ int   g_bsumx[64];
__device__ int   g_rowptr[NN + 1];
__device__ int   g_wp[NN];
__device__ int   g_esrc[NE];          // CSR: src node per slot
__device__ int   g_bound[NG + 1];
__device__ float g_inv_cnt[NG];

static inline int cdiv(int a, int b) { return (a + b - 1) / b; }

// ---- f32x2 helpers (FFMA2 only reachable via PTX) ----
typedef unsigned long long u64;
__device__ __forceinline__ u64 pk(float lo, float hi) {
    u64 r; asm("mov.b64 %0,{%1,%2};" : "=l"(r) : "f"(lo), "f"(hi)); return r;
}
__device__ __forceinline__ float2 upk(u64 v) {
    float2 f; asm("mov.b64 {%0,%1},%2;" : "=f"(f.x), "=f"(f.y) : "l"(v)); return f;
}
__device__ __forceinline__ void fma2(u64& d, u64 a, u64 b) {
    asm("fma.rn.f32x2 %0,%1,%2,%0;" : "+l"(d) : "l"(a), "l"(b));
}

// ================= CSR build =================
__global__ void izero_kernel(int* __restrict__ p, int n) {
    int i = blockIdx.x * blockDim.x + threadIdx.x;
    if (i < n) p[i] = 0;
}

__global__ void hist_kernel(const int* __restrict__ dst) {
    int i = blockIdx.x * blockDim.x + threadIdx.x;
    if (i < NE) atomicAdd(&g_cnt[dst[i]], 1);
}

__global__ void __launch_bounds__(SCAN_B) scan1_kernel() {
    __shared__ int s[SCAN_B];
    int tid = threadIdx.x;
    int i = blockIdx.x * SCAN_B + tid;
    int v = (i < NN) ? g_cnt[i] : 0;
    s[tid] = v;
    __syncthreads();
    for (int off = 1; off < SCAN_B; off <<= 1) {
        int t = (tid >= off) ? s[tid - off] : 0;
        __syncthreads();
        s[tid] += t;
        __syncthreads();
    }
    g_excl[i] = s[tid] - v;                 // exclusive within block
    if (tid == SCAN_B - 1) g_bsum[blockIdx.x] = s[tid];
}

__global__ void scan2_kernel() {            // 1 block, 64 threads over 49 sums
    __shared__ int s[64];
    int tid = threadIdx.x;
    int v = (tid < NBLK) ? g_bsum[tid] : 0;
    s[tid] = v;
    __syncthreads();
    for (int off = 1; off < 64; off <<= 1) {
        int t = (tid >= off) ? s[tid - off] : 0;
        __syncthreads();
        s[tid] += t;
        __syncthreads();
    }
    g_bsumx[tid] = s[tid] - v;              // exclusive block offsets
}

__global__ void scan3_kernel() {            // row_ptr + wp copy
    int i = blockIdx.x * blockDim.x + threadIdx.x;
    if (i < NN) {
        int rp = g_excl[i] + g_bsumx[i >> 10];
        g_rowptr[i] = rp;
        g_wp[i] = rp;
    } else if (i == NN) {
        g_rowptr[NN] = NE;
    }
}

__global__ void fill_kernel(const int* __restrict__ src, const int* __restrict__ dst) {
    int i = blockIdx.x * blockDim.x + threadIdx.x;
    if (i < NE) {
        int pos = atomicAdd(&g_wp[dst[i]], 1);
        g_esrc[pos] = src[i];
    }
}

// ---- graph boundaries via binary search on sorted batch ----
__global__ void bounds_kernel(const int* __restrict__ batch) {
    __shared__ int b[NG + 1];
    int g = threadIdx.x;
    if (g <= NG) {
        int lo = 0, hi = NN;
        while (lo < hi) {
            int mid = (lo + hi) >> 1;
            if (batch[mid] < g) lo = mid + 1; else hi = mid;
        }
        g_bound[g] = lo;
        b[g] = lo;
    }
    __syncthreads();
    if (g < NG)
        g_inv_cnt[g] = 1.0f / fmaxf((float)(b[g + 1] - b[g]), 1.0f);
}

// ================= mean aggregation: one warp per node (CSR gather) =============
__global__ void __launch_bounds__(256) gather_kernel(const float* __restrict__ x) {
    int node = (blockIdx.x * blockDim.x + threadIdx.x) >> 5;
    int lane = threadIdx.x & 31;
    if (node >= NN) return;
    int beg = g_rowptr[node], end = g_rowptr[node + 1];
    float a0 = 0.f, a1 = 0.f, a2 = 0.f;
    float b0 = 0.f, b1 = 0.f, b2 = 0.f;
    int e = beg;
    for (; e + 1 < end; e += 2) {
        int s0 = g_esrc[e], s1 = g_esrc[e + 1];
        const float* r0 = x + (size_t)s0 * DIN;
        const float* r1 = x + (size_t)s1 * DIN;
        float v00 = __ldg(r0 + lane), v01 = __ldg(r0 + lane + 32), v02 = __ldg(r0 + lane + 64);
        float v10 = __ldg(r1 + lane), v11 = __ldg(r1 + lane + 32), v12 = __ldg(r1 + lane + 64);
        a0 += v00; a1 += v01; a2 += v02;
        b0 += v10; b1 += v11; b2 += v12;
    }
    if (e < end) {
        const float* r0 = x + (size_t)g_esrc[e] * DIN;
        a0 += __ldg(r0 + lane); a1 += __ldg(r0 + lane + 32); a2 += __ldg(r0 + lane + 64);
    }
    float inv = 1.0f / fmaxf((float)(end - beg), 1.0f);
    float* ar = g_agg + (size_t)node * DIN;
    ar[lane]      = (a0 + b0) * inv;
    ar[lane + 32] = (a1 + b1) * inv;
    ar[lane + 64] = (a2 + b2) * inv;
}

// ================= fused SAGE layer GEMM (f32x2) =================
// out[n][j] = relu?( b[j] + sum_k mean[n][k]*Wl[j][k] + x[n][k]*Wr[j][k] )
// 64-node tile, 512 threads = 16(tx:j-pairs) x 32(ty:nodes); thread: 2 nodes x NJP j-pairs.
template<int DOUT, bool RELU>
__global__ void __launch_bounds__(512)
sage_gemm(const float* __restrict__ xin,
          const float* __restrict__ mean,
          const float* __restrict__ Wl,
          const float* __restrict__ bias,
          const float* __restrict__ Wr,
          float* __restrict__ out) {
    constexpr int WP  = DOUT + 2;     // even pitch -> aligned LDS.64 on j-pairs
    constexpr int NJP = DOUT / 32;    // j-pairs per thread (96->3, 64->2)
    constexpr int AP  = 2 * DIN + 4;  // 196: interleaved (mean,x) row pitch, 8B-aligned
    extern __shared__ float sm[];
    float* Wlt = sm;                   // [DIN][WP]  k-major
    float* Wrt = Wlt + DIN * WP;
    float* bs  = Wrt + DIN * WP;       // [DOUT]
    float* A   = bs + DOUT;            // [64][AP]   A[n][2k]=mean, A[n][2k+1]=x

    int tid = threadIdx.x;
    for (int idx = tid; idx < DOUT * DIN; idx += 512) {
        int j = idx / DIN, k = idx - j * DIN;
        Wlt[k * WP + j] = Wl[idx];
        Wrt[k * WP + j] = Wr[idx];
    }
    if (tid < DOUT) bs[tid] = bias[tid];

    int node0 = blockIdx.x * 64;
    for (int idx = tid; idx < 64 * DIN; idx += 512) {
        int n = idx / DIN, k = idx - n * DIN;
        int node = node0 + n;
        float m = 0.f, xv = 0.f;
        if (node < NN) {
            m  = mean[(size_t)node * DIN + k];
            xv = xin[(size_t)node * DIN + k];
        }
        A[n * AP + 2 * k]     = m;
        A[n * AP + 2 * k + 1] = xv;
    }
    __syncthreads();

    int tx = tid & 15, ty = tid >> 4;       // tx: j-pair group, ty: node 0..31
    u64 acc[2][NJP];
#pragma unroll
    for (int jj = 0; jj < NJP; jj++) {
        float2 bp = *(const float2*)&bs[2 * tx + 32 * jj];
        u64 bv = pk(bp.x, bp.y);
        acc[0][jj] = bv;
        acc[1][jj] = bv;
    }

#pragma unroll 4
    for (int k = 0; k < DIN; k++) {
        u64 am2[2], ax2[2];
#pragma unroll
        for (int nn = 0; nn < 2; nn++) {
            float2 p = *(const float2*)&A[(nn * 32 + ty) * AP + 2 * k];
            am2[nn] = pk(p.x, p.x);
            ax2[nn] = pk(p.y, p.y);
        }
#pragma unroll
        for (int jj = 0; jj < NJP; jj++) {
            u64 wl2 = *(const u64*)&Wlt[k * WP + 2 * tx + 32 * jj];
            u64 wr2 = *(const u64*)&Wrt[k * WP + 2 * tx + 32 * jj];
#pragma unroll
            for (int nn = 0; nn < 2; nn++) {
                fma2(acc[nn][jj], am2[nn], wl2);
                fma2(acc[nn][jj], ax2[nn], wr2);
            }
        }
    }

#pragma unroll
    for (int nn = 0; nn < 2; nn++) {
        int node = node0 + nn * 32 + ty;
        if (node < NN) {
#pragma unroll
            for (int jj = 0; jj < NJP; jj++) {
                float2 v = upk(acc[nn][jj]);
                if (RELU) { v.x = fmaxf(v.x, 0.f); v.y = fmaxf(v.y, 0.f); }
                *(float2*)&out[(size_t)node * DOUT + 2 * tx + 32 * jj] = v;
            }
        }
    }
}

// ================= pool: block per graph, no atomics =================
__global__ void __launch_bounds__(256) pool_kernel(const float* __restrict__ h,
                                                   float* __restrict__ out) {
    __shared__ float red[256];
    int g = blockIdx.x;
    int beg = g_bound[g], end = g_bound[g + 1];
    int col = threadIdx.x & 63, chunk = threadIdx.x >> 6;  // 4 chunks
    float s = 0.f;
    for (int n = beg + chunk; n < end; n += 4)
        s += h[(size_t)n * 64 + col];
    red[threadIdx.x] = s;
    __syncthreads();
    if (threadIdx.x < 64) {
        float v = red[threadIdx.x] + red[threadIdx.x + 64] +
                  red[threadIdx.x + 128] + red[threadIdx.x + 192];
        out[g * 64 + threadIdx.x] = v * g_inv_cnt[g];
    }
}

extern "C" void kernel_launch(void* const* d_in, const int* in_sizes, int n_in,
                              void* d_out, int out_size) {
    const float* x     = (const float*)d_in[0];
    const int*   ei    = (const int*)d_in[1];
    const int*   batch = (const int*)d_in[2];
    const float* Wl0 = (const float*)d_in[3];
    const float* b0  = (const float*)d_in[4];
    const float* Wr0 = (const float*)d_in[5];
    const float* Wl1 = (const float*)d_in[6];
    const float* b1  = (const float*)d_in[7];
    const float* Wr1 = (const float*)d_in[8];
    const float* Wl2 = (const float*)d_in[9];
    const float* b2  = (const float*)d_in[10];
    const float* Wr2 = (const float*)d_in[11];
    float* out = (float*)d_out;

    const int* srcp = ei;
    const int* dstp = ei + NE;

    float *agg, *ha, *hb;
    int* cnt;
    cudaGetSymbolAddress((void**)&agg, g_agg);
    cudaGetSymbolAddress((void**)&ha,  g_ha);
    cudaGetSymbolAddress((void**)&hb,  g_hb);
    cudaGetSymbolAddress((void**)&cnt, g_cnt);

    const int SMEM96 = (2 * DIN * 98 + 96 + 64 * 196) * (int)sizeof(float);
    const int SMEM64 = (2 * DIN * 66 + 64 + 64 * 196) * (int)sizeof(float);
    cudaFuncSetAttribute(sage_gemm<96, true>,
                         cudaFuncAttributeMaxDynamicSharedMemorySize, SMEM96);
    cudaFuncSetAttribute(sage_gemm<64, false>,
                         cudaFuncAttributeMaxDynamicSharedMemorySize, SMEM64);

    const int T = 256;
    int gemm_grid = cdiv(NN, 64);
    int gather_grid = cdiv(NN * 32, T);

    // ---- CSR build (shared by all 3 layers) + graph bounds ----
    izero_kernel<<<cdiv(NN, T), T>>>(cnt, NN);
    hist_kernel<<<cdiv(NE, T), T>>>(dstp);
    scan1_kernel<<<NBLK, SCAN_B>>>();
    scan2_kernel<<<1, 64>>>();
    scan3_kernel<<<cdiv(NN + 1, T), T>>>();
    fill_kernel<<<cdiv(NE, T), T>>>(srcp, dstp);
    bounds_kernel<<<1, 256>>>(batch);

    // ---- layer 0: x -> ha ----
    gather_kernel<<<gather_grid, T>>>(x);
    sage_gemm<96, true><<<gemm_grid, 512, SMEM96>>>(x, agg, Wl0, b0, Wr0, ha);

    // ---- layer 1: ha -> hb ----
    gather_kernel<<<gather_grid, T>>>(ha);
    sage_gemm<96, true><<<gemm_grid, 512, SMEM96>>>(ha, agg, Wl1, b1, Wr1, hb);

    // ---- layer 2: hb -> ha ([NN,64]) ----
    gather_kernel<<<gather_grid, T>>>(hb);
    sage_gemm<64, false><<<gemm_grid, 512, SMEM64>>>(hb, agg, Wl2, b2, Wr2, ha);

    // ---- global mean pool ----
    pool_kernel<<<NG, 256>>>(ha, out);
}

// round 4
// speedup vs baseline: 1.6048x; 1.1399x over previous
#include <cuda_runtime.h>

#define NN 50000
#define NE 800000
#define NG 128
#define DIN 96
#define SCAN_B 1024
#define NBLK ((NN + SCAN_B - 1) / SCAN_B)   // 49

// ---- scratch (__device__ globals; no allocs allowed) ----
__device__ float g_agg[NN * DIN];
__device__ float g_ha[NN * DIN];
__device__ float g_hb[NN * DIN];
__device__ int   g_cnt[NN];
__device__ int   g_excl[NBLK * SCAN_B];
__device__ int   g_bsum[64];
__device__ int   g_bsumx[64];
__device__ int   g_rowptr[NN + 1];
__device__ int   g_wp[NN];
__device__ int   g_esrc[NE];
__device__ int   g_bound[NG + 1];
__device__ float g_inv_cnt[NG];

static inline int cdiv(int a, int b) { return (a + b - 1) / b; }

// ---- f32x2 helpers (FFMA2 only reachable via PTX) ----
typedef unsigned long long u64;
__device__ __forceinline__ u64 pk(float lo, float hi) {
    u64 r; asm("mov.b64 %0,{%1,%2};" : "=l"(r) : "f"(lo), "f"(hi)); return r;
}
__device__ __forceinline__ float2 upk(u64 v) {
    float2 f; asm("mov.b64 {%0,%1},%2;" : "=f"(f.x), "=f"(f.y) : "l"(v)); return f;
}
__device__ __forceinline__ void fma2(u64& d, u64 a, u64 b) {
    asm("fma.rn.f32x2 %0,%1,%2,%0;" : "+l"(d) : "l"(a), "l"(b));
}

// ================= CSR build =================
__global__ void izero_kernel(int* __restrict__ p, int n) {
    int i = blockIdx.x * blockDim.x + threadIdx.x;
    if (i < n) p[i] = 0;
}

__global__ void hist_kernel(const int* __restrict__ dst) {
    int i = blockIdx.x * blockDim.x + threadIdx.x;
    if (i < NE) atomicAdd(&g_cnt[dst[i]], 1);
}

__global__ void __launch_bounds__(SCAN_B) scan1_kernel() {
    __shared__ int s[SCAN_B];
    int tid = threadIdx.x;
    int i = blockIdx.x * SCAN_B + tid;
    int v = (i < NN) ? g_cnt[i] : 0;
    s[tid] = v;
    __syncthreads();
    for (int off = 1; off < SCAN_B; off <<= 1) {
        int t = (tid >= off) ? s[tid - off] : 0;
        __syncthreads();
        s[tid] += t;
        __syncthreads();
    }
    g_excl[i] = s[tid] - v;
    if (tid == SCAN_B - 1) g_bsum[blockIdx.x] = s[tid];
}

__global__ void scan2_kernel() {
    __shared__ int s[64];
    int tid = threadIdx.x;
    int v = (tid < NBLK) ? g_bsum[tid] : 0;
    s[tid] = v;
    __syncthreads();
    for (int off = 1; off < 64; off <<= 1) {
        int t = (tid >= off) ? s[tid - off] : 0;
        __syncthreads();
        s[tid] += t;
        __syncthreads();
    }
    g_bsumx[tid] = s[tid] - v;
}

__global__ void scan3_kernel() {
    int i = blockIdx.x * blockDim.x + threadIdx.x;
    if (i < NN) {
        int rp = g_excl[i] + g_bsumx[i >> 10];
        g_rowptr[i] = rp;
        g_wp[i] = rp;
    } else if (i == NN) {
        g_rowptr[NN] = NE;
    }
}

__global__ void fill_kernel(const int* __restrict__ src, const int* __restrict__ dst) {
    int i = blockIdx.x * blockDim.x + threadIdx.x;
    if (i < NE) {
        int pos = atomicAdd(&g_wp[dst[i]], 1);
        g_esrc[pos] = src[i];
    }
}

__global__ void bounds_kernel(const int* __restrict__ batch) {
    __shared__ int b[NG + 1];
    int g = threadIdx.x;
    if (g <= NG) {
        int lo = 0, hi = NN;
        while (lo < hi) {
            int mid = (lo + hi) >> 1;
            if (batch[mid] < g) lo = mid + 1; else hi = mid;
        }
        g_bound[g] = lo;
        b[g] = lo;
    }
    __syncthreads();
    if (g < NG)
        g_inv_cnt[g] = 1.0f / fmaxf((float)(b[g + 1] - b[g]), 1.0f);
}

// ========== mean aggregation: warp/node, shfl-broadcast indices, float4 loads =====
__global__ void __launch_bounds__(256) gather_kernel(const float* __restrict__ x) {
    int node = (blockIdx.x * blockDim.x + threadIdx.x) >> 5;
    int lane = threadIdx.x & 31;
    if (node >= NN) return;
    int beg = g_rowptr[node], end = g_rowptr[node + 1];

    float4 acc = make_float4(0.f, 0.f, 0.f, 0.f);
    const float4* __restrict__ x4 = (const float4*)x;   // row = 24 float4
    bool act = lane < 24;

    for (int base = beg; base < end; base += 32) {
        int cnt = end - base;
        if (cnt > 32) cnt = 32;
        int myidx = g_esrc[base + (lane < cnt ? lane : 0)];
        int j = 0;
        for (; j + 4 <= cnt; j += 4) {
            int s0 = __shfl_sync(0xffffffffu, myidx, j);
            int s1 = __shfl_sync(0xffffffffu, myidx, j + 1);
            int s2 = __shfl_sync(0xffffffffu, myidx, j + 2);
            int s3 = __shfl_sync(0xffffffffu, myidx, j + 3);
            if (act) {
                float4 v0 = __ldg(&x4[(size_t)s0 * 24 + lane]);
                float4 v1 = __ldg(&x4[(size_t)s1 * 24 + lane]);
                float4 v2 = __ldg(&x4[(size_t)s2 * 24 + lane]);
                float4 v3 = __ldg(&x4[(size_t)s3 * 24 + lane]);
                acc.x += v0.x + v1.x + v2.x + v3.x;
                acc.y += v0.y + v1.y + v2.y + v3.y;
                acc.z += v0.z + v1.z + v2.z + v3.z;
                acc.w += v0.w + v1.w + v2.w + v3.w;
            }
        }
        for (; j < cnt; j++) {
            int s0 = __shfl_sync(0xffffffffu, myidx, j);
            if (act) {
                float4 v0 = __ldg(&x4[(size_t)s0 * 24 + lane]);
                acc.x += v0.x; acc.y += v0.y; acc.z += v0.z; acc.w += v0.w;
            }
        }
    }
    if (act) {
        float inv = 1.0f / fmaxf((float)(end - beg), 1.0f);
        acc.x *= inv; acc.y *= inv; acc.z *= inv; acc.w *= inv;
        ((float4*)(g_agg + (size_t)node * DIN))[lane] = acc;
    }
}

// ================= fused SAGE layer GEMM (f32x2, pre-duplicated A) =================
// out[n][j] = relu?( b[j] + sum_k mean[n][k]*Wl[j][k] + x[n][k]*Wr[j][k] )
// 64-node tile, 256 threads = 16(tx) x 16(ty); thread: 4 nodes x NJP j-pairs.
// smem A stores duplicated pairs: A[n][4k..4k+3] = {m,m,x,x} -> LDS.64 yields bcast pair.
template<int DOUT, bool RELU>
__global__ void __launch_bounds__(256)
sage_gemm(const float* __restrict__ xin,
          const float* __restrict__ mean,
          const float* __restrict__ Wl,
          const float* __restrict__ bias,
          const float* __restrict__ Wr,
          float* __restrict__ out) {
    constexpr int WP  = DOUT + 2;
    constexpr int NJP = DOUT / 32;    // 3 (d=96) or 2 (d=64)
    constexpr int AP  = 4 * DIN + 4;  // 388 floats, even pitch
    extern __shared__ float sm[];
    float* Wlt = sm;                   // [DIN][WP] k-major
    float* Wrt = Wlt + DIN * WP;
    float* bs  = Wrt + DIN * WP;       // [DOUT]
    float* A   = bs + DOUT;            // [64][AP]

    int tid = threadIdx.x;
    for (int idx = tid; idx < DOUT * DIN; idx += 256) {
        int j = idx / DIN, k = idx - j * DIN;
        Wlt[k * WP + j] = Wl[idx];
        Wrt[k * WP + j] = Wr[idx];
    }
    if (tid < DOUT) bs[tid] = bias[tid];

    int node0 = blockIdx.x * 64;
    for (int idx = tid; idx < 64 * DIN; idx += 256) {
        int n = idx / DIN, k = idx - n * DIN;
        int node = node0 + n;
        float m = 0.f, xv = 0.f;
        if (node < NN) {
            m  = mean[(size_t)node * DIN + k];
            xv = xin[(size_t)node * DIN + k];
        }
        *(float2*)&A[n * AP + 4 * k]     = make_float2(m, m);
        *(float2*)&A[n * AP + 4 * k + 2] = make_float2(xv, xv);
    }
    __syncthreads();

    int tx = tid & 15, ty = tid >> 4;
    u64 acc[4][NJP];
#pragma unroll
    for (int jj = 0; jj < NJP; jj++) {
        float2 bp = *(const float2*)&bs[2 * tx + 32 * jj];
        u64 bv = pk(bp.x, bp.y);
#pragma unroll
        for (int nn = 0; nn < 4; nn++) acc[nn][jj] = bv;
    }

#pragma unroll 2
    for (int k = 0; k < DIN; k++) {
        u64 am2[4], ax2[4];
#pragma unroll
        for (int nn = 0; nn < 4; nn++) {
            const float* ap = &A[(nn * 16 + ty) * AP + 4 * k];
            am2[nn] = *(const u64*)(ap);
            ax2[nn] = *(const u64*)(ap + 2);
        }
#pragma unroll
        for (int jj = 0; jj < NJP; jj++) {
            u64 wl2 = *(const u64*)&Wlt[k * WP + 2 * tx + 32 * jj];
            u64 wr2 = *(const u64*)&Wrt[k * WP + 2 * tx + 32 * jj];
#pragma unroll
            for (int nn = 0; nn < 4; nn++) {
                fma2(acc[nn][jj], am2[nn], wl2);
                fma2(acc[nn][jj], ax2[nn], wr2);
            }
        }
    }

#pragma unroll
    for (int nn = 0; nn < 4; nn++) {
        int node = node0 + nn * 16 + ty;
        if (node < NN) {
#pragma unroll
            for (int jj = 0; jj < NJP; jj++) {
                float2 v = upk(acc[nn][jj]);
                if (RELU) { v.x = fmaxf(v.x, 0.f); v.y = fmaxf(v.y, 0.f); }
                *(float2*)&out[(size_t)node * DOUT + 2 * tx + 32 * jj] = v;
            }
        }
    }
}

// ================= pool: block per graph, no atomics =================
__global__ void __launch_bounds__(256) pool_kernel(const float* __restrict__ h,
                                                   float* __restrict__ out) {
    __shared__ float red[256];
    int g = blockIdx.x;
    int beg = g_bound[g], end = g_bound[g + 1];
    int col = threadIdx.x & 63, chunk = threadIdx.x >> 6;
    float s = 0.f;
    for (int n = beg + chunk; n < end; n += 4)
        s += h[(size_t)n * 64 + col];
    red[threadIdx.x] = s;
    __syncthreads();
    if (threadIdx.x < 64) {
        float v = red[threadIdx.x] + red[threadIdx.x + 64] +
                  red[threadIdx.x + 128] + red[threadIdx.x + 192];
        out[g * 64 + threadIdx.x] = v * g_inv_cnt[g];
    }
}

extern "C" void kernel_launch(void* const* d_in, const int* in_sizes, int n_in,
                              void* d_out, int out_size) {
    const float* x     = (const float*)d_in[0];
    const int*   ei    = (const int*)d_in[1];
    const int*   batch = (const int*)d_in[2];
    const float* Wl0 = (const float*)d_in[3];
    const float* b0  = (const float*)d_in[4];
    const float* Wr0 = (const float*)d_in[5];
    const float* Wl1 = (const float*)d_in[6];
    const float* b1  = (const float*)d_in[7];
    const float* Wr1 = (const float*)d_in[8];
    const float* Wl2 = (const float*)d_in[9];
    const float* b2  = (const float*)d_in[10];
    const float* Wr2 = (const float*)d_in[11];
    float* out = (float*)d_out;

    const int* srcp = ei;
    const int* dstp = ei + NE;

    float *agg, *ha, *hb;
    int* cnt;
    cudaGetSymbolAddress((void**)&agg, g_agg);
    cudaGetSymbolAddress((void**)&ha,  g_ha);
    cudaGetSymbolAddress((void**)&hb,  g_hb);
    cudaGetSymbolAddress((void**)&cnt, g_cnt);

    const int SMEM96 = (2 * DIN * 98 + 96 + 64 * (4 * DIN + 4)) * (int)sizeof(float);
    const int SMEM64 = (2 * DIN * 66 + 64 + 64 * (4 * DIN + 4)) * (int)sizeof(float);
    cudaFuncSetAttribute(sage_gemm<96, true>,
                         cudaFuncAttributeMaxDynamicSharedMemorySize, SMEM96);
    cudaFuncSetAttribute(sage_gemm<64, false>,
                         cudaFuncAttributeMaxDynamicSharedMemorySize, SMEM64);

    const int T = 256;
    int gemm_grid = cdiv(NN, 64);
    int gather_grid = cdiv(NN * 32, T);

    // ---- CSR build (shared by all 3 layers) + graph bounds ----
    izero_kernel<<<cdiv(NN, T), T>>>(cnt, NN);
    hist_kernel<<<cdiv(NE, T), T>>>(dstp);
    scan1_kernel<<<NBLK, SCAN_B>>>();
    scan2_kernel<<<1, 64>>>();
    scan3_kernel<<<cdiv(NN + 1, T), T>>>();
    fill_kernel<<<cdiv(NE, T), T>>>(srcp, dstp);
    bounds_kernel<<<1, 256>>>(batch);

    // ---- layer 0: x -> ha ----
    gather_kernel<<<gather_grid, T>>>(x);
    sage_gemm<96, true><<<gemm_grid, 256, SMEM96>>>(x, agg, Wl0, b0, Wr0, ha);

    // ---- layer 1: ha -> hb ----
    gather_kernel<<<gather_grid, T>>>(ha);
    sage_gemm<96, true><<<gemm_grid, 256, SMEM96>>>(ha, agg, Wl1, b1, Wr1, hb);

    // ---- layer 2: hb -> ha ([NN,64]) ----
    gather_kernel<<<gather_grid, T>>>(hb);
    sage_gemm<64, false><<<gemm_grid, 256, SMEM64>>>(hb, agg, Wl2, b2, Wr2, ha);

    // ---- global mean pool ----
    pool_kernel<<<NG, 256>>>(ha, out);
}